// round 4
// baseline (speedup 1.0000x reference)
#include <cuda_runtime.h>
#include <cuda_bf16.h>

// MeshNN: u(x) = linear interp of fused weights W = [w_dd0, w_uu..., w_dd1]
// on a UNIFORM 512-node grid (coords = linspace). Node positions are analytic:
//   t_global = (x - c0) * inv_h;  j = floor(t_global);  t = t_global - j;
//   u = W[j] + t*(W[j+1]-W[j])
// (exactly the reference hat-basis result; analytic-vs-linspace fp32 node error
//  is <=1 ulp -> output error ~3e-5 absolute, far below the 1e-3 tolerance).
// Weights staged in shared; staging + x DRAM load overlap before the barrier.

#define NP_NODES 512

__global__ __launch_bounds__(256) void meshnn_kernel(
    const float2* __restrict__ x2,
    const float*  __restrict__ coords,
    const float*  __restrict__ w_uu,
    const float*  __restrict__ w_dd,
    float2*       __restrict__ out2,
    int n2)
{
    __shared__ float wsh[NP_NODES];

    int gid = blockIdx.x * blockDim.x + threadIdx.x;

    // Issue the DRAM load for x first so it overlaps the weight staging.
    float2 xin = make_float2(0.0f, 0.0f);
    if (gid < n2) xin = __ldg(&x2[gid]);

    // Stage fused weight vector into shared (coalesced, hits L2 after wave start).
    for (int i = threadIdx.x; i < NP_NODES; i += 256) {
        float w;
        if (i == 0)                 w = __ldg(&w_dd[0]);
        else if (i == NP_NODES - 1) w = __ldg(&w_dd[1]);
        else                        w = __ldg(&w_uu[i - 1]);
        wsh[i] = w;
    }

    const float c0    = __ldg(&coords[0]);
    const float cL    = __ldg(&coords[NP_NODES - 1]);
    const float inv_h = (float)(NP_NODES - 1) / (cL - c0);

    __syncthreads();
    if (gid >= n2) return;

    float tg0 = (xin.x - c0) * inv_h;
    float tg1 = (xin.y - c0) * inv_h;

    int j0 = min(max((int)tg0, 0), NP_NODES - 2);
    int j1 = min(max((int)tg1, 0), NP_NODES - 2);

    float t0 = tg0 - (float)j0;
    float t1 = tg1 - (float)j1;

    float a0 = wsh[j0], b0 = wsh[j0 + 1];
    float a1 = wsh[j1], b1 = wsh[j1 + 1];

    float2 r;
    r.x = fmaf(t0, b0 - a0, a0);
    r.y = fmaf(t1, b1 - a1, a1);
    out2[gid] = r;
}

extern "C" void kernel_launch(void* const* d_in, const int* in_sizes, int n_in,
                              void* d_out, int out_size)
{
    const float* x      = (const float*)d_in[0];
    const float* coords = (const float*)d_in[1];
    const float* w_uu   = (const float*)d_in[2];
    const float* w_dd   = (const float*)d_in[3];
    float* out = (float*)d_out;

    int n  = in_sizes[0];   // 262144
    int n2 = n >> 1;        // 131072 float2 elements

    int threads = 256;
    int blocks  = (n2 + threads - 1) / threads;   // 512
    meshnn_kernel<<<blocks, threads>>>(
        (const float2*)x, coords, w_uu, w_dd, (float2*)out, n2);
}